// round 14
// baseline (speedup 1.0000x reference)
#include <cuda_runtime.h>
#include <cuda_bf16.h>
#include <stdint.h>
#include <math.h>

// Volume: D=64, H=128, W=128 ; B=2, C=4  (fixed shapes)
#define DZ 64
#define HY 128
#define WX 128
#define NVOX (DZ * HY * WX)   // 1,048,576
#define NROWS 8192            // DZ*HY rows of 128 voxels
#define NMASK 12
#define NPROB 36
#define RCAP (NROWS * 64)     // run slots per problem = 524288
#define ZSLAB 4               // z-planes per slab
#define NSLAB (DZ / ZSLAB)    // 16
#define SROWS (ZSLAB * HY)    // 512 rows per slab
#define SRUN  (SROWS * 64)    // 32768 run slots per slab
#define SEN  0x7F7F7F7F       // global sentinel (>= RCAP -> root)
#define LSEN 0x7FFFFFFF       // slab-local sentinel (>= SRUN -> root)

typedef unsigned int u32;
typedef unsigned long long u64;
typedef unsigned char u8;

// Scratch (device globals)
__device__ uint4 g_mbits[NMASK][NROWS];      // mask bitmaps, 16B/row
__device__ uint4 g_ebits[NMASK][NROWS];      // eroded bitmaps
__device__ int   g_P[(size_t)NPROB * RCAP];  // run-level UF parents (written by k_slab)
__device__ u8    g_R[(size_t)NMASK * RCAP];  // bg run border-reach flags
__device__ int   g_cnt[NPROB];

// ---------------- 128-bit row helpers ----------------
struct B128 { u64 lo, hi; };

__device__ __forceinline__ B128 b_load(const uint4* arr, int row) {
    uint4 q = arr[row];
    B128 r;
    r.lo = (u64)q.x | ((u64)q.y << 32);
    r.hi = (u64)q.z | ((u64)q.w << 32);
    return r;
}
__device__ __forceinline__ void b_store(uint4* arr, int row, B128 v) {
    arr[row] = make_uint4((u32)v.lo, (u32)(v.lo >> 32), (u32)v.hi, (u32)(v.hi >> 32));
}
__device__ __forceinline__ B128 b_and(B128 a, B128 b) { return {a.lo & b.lo, a.hi & b.hi}; }
__device__ __forceinline__ B128 b_not(B128 a) { return {~a.lo, ~a.hi}; }
__device__ __forceinline__ B128 b_shl1(B128 a) { return {a.lo << 1, (a.hi << 1) | (a.lo >> 63)}; }
__device__ __forceinline__ B128 b_shr1(B128 a) { return {(a.lo >> 1) | (a.hi << 63), a.hi >> 1}; }
__device__ __forceinline__ bool b_any(B128 a) { return (a.lo | a.hi) != 0ULL; }
__device__ __forceinline__ int  b_pop(B128 a) { return __popcll(a.lo) + __popcll(a.hi); }
__device__ __forceinline__ B128 b_starts(B128 o) { B128 s = b_shl1(o); return {o.lo & ~s.lo, o.hi & ~s.hi}; }
// popcount of start bits strictly below global bit position b (b in [0,128])
__device__ __forceinline__ int b_popbelow(B128 s, int b) {
    if (b == 0) return 0;
    if (b <= 64) {
        u64 m = (b == 64) ? ~0ULL : ((1ULL << b) - 1ULL);
        return __popcll(s.lo & m);
    }
    int bb = b - 64;
    u64 m = (bb >= 64) ? ~0ULL : ((1ULL << bb) - 1ULL);
    return __popcll(s.lo) + __popcll(s.hi & m);
}
__device__ __forceinline__ int cto64(u64 x) {
    u64 inv = ~x;
    return inv ? (__ffsll((long long)inv) - 1) : 64;
}
__device__ __forceinline__ int b_runlen(B128 o, int b) {
    B128 sh;
    if (b == 0) sh = o;
    else if (b < 64) { sh.lo = (o.lo >> b) | (o.hi << (64 - b)); sh.hi = o.hi >> b; }
    else { sh.lo = o.hi >> (b - 64); sh.hi = 0; }
    int c = cto64(sh.lo);
    if (c == 64) c += cto64(sh.hi);
    return c;
}

// ---------------- global union-find (sentinel roots: P[x] >= RCAP) --------
__device__ __forceinline__ int uf_find(int* P, int x) {
    while (true) {
        int p = P[x];
        if (p >= RCAP) return x;
        int gp = P[p];
        if (gp >= RCAP) return p;
        P[x] = gp;
        x = gp;
    }
}
__device__ __forceinline__ void uf_union(int* P, int a, int b) {
    while (true) {
        a = uf_find(P, a);
        b = uf_find(P, b);
        if (a == b) return;
        if (a > b) { int t = a; a = b; b = t; }
        int old = atomicMin(&P[b], a);
        if (old >= RCAP || old == b) return;
        b = old;
    }
}

// ---------------- slab-local union-find (shared; roots: >= SRUN) ----------
__device__ __forceinline__ int l_find(int* P, int x) {
    while (true) {
        int p = P[x];
        if (p >= SRUN) return x;
        int gp = P[p];
        if (gp >= SRUN) return p;
        P[x] = gp;
        x = gp;
    }
}
__device__ __forceinline__ void l_union(int* P, int a, int b) {
    while (true) {
        a = l_find(P, a);
        b = l_find(P, b);
        if (a == b) return;
        if (a > b) { int t = a; a = b; b = t; }
        int old = atomicMin(&P[b], a);
        if (old >= SRUN || old == b) return;
        b = old;
    }
}

// occupancy for problem p, row r
__device__ __forceinline__ B128 get_occ(int p, int row) {
    if (p < 12) return b_load(g_mbits[p], row);
    if (p < 24) return b_load(g_ebits[p - 12], row);
    return b_not(b_load(g_mbits[p - 24], row));
}

// ---------------- kernels ----------------

// Warp per (batch,row): softmax+threshold -> 6 bitmap rows.  grid 2048 x 256
__global__ void k_masks(const float* __restrict__ pred, const int* __restrict__ target) {
    int gw = blockIdx.x * 8 + (threadIdx.x >> 5);
    int lane = threadIdx.x & 31;
    int b = gw >> 13;
    int row = gw & (NROWS - 1);
    int v = row * WX + lane * 4;

    const float* pp = pred + (size_t)b * 4 * NVOX + v;
    float4 a0 = *(const float4*)(pp);
    float4 a1 = *(const float4*)(pp + NVOX);
    float4 a2 = *(const float4*)(pp + 2 * NVOX);
    float4 a3 = *(const float4*)(pp + 3 * NVOX);
    int4 t = *(const int4*)(target + (size_t)b * NVOX + v);

    float x0s[4] = {a0.x, a0.y, a0.z, a0.w};
    float x1s[4] = {a1.x, a1.y, a1.z, a1.w};
    float x2s[4] = {a2.x, a2.y, a2.z, a2.w};
    float x3s[4] = {a3.x, a3.y, a3.z, a3.w};
    u32 nib[6] = {0, 0, 0, 0, 0, 0};
    #pragma unroll
    for (int i = 0; i < 4; i++) {
        float m = fmaxf(fmaxf(x0s[i], x1s[i]), fmaxf(x2s[i], x3s[i]));
        float e0 = expf(x0s[i] - m), e1 = expf(x1s[i] - m);
        float e2 = expf(x2s[i] - m), e3 = expf(x3s[i] - m);
        float h = 0.5f * (e0 + e1 + e2 + e3);
        nib[0] |= (e1 > h) << i;
        nib[1] |= (e2 > h) << i;
        nib[2] |= (e3 > h) << i;
    }
    int ts[4] = {t.x, t.y, t.z, t.w};
    #pragma unroll
    for (int i = 0; i < 4; i++) {
        nib[3] |= (ts[i] == 1) << i;
        nib[4] |= (ts[i] == 2) << i;
        nib[5] |= (ts[i] == 3) << i;
    }
    int sh = (lane & 7) * 4;
    int widx = lane >> 3;
    #pragma unroll
    for (int k = 0; k < 6; k++) {
        u32 seg = nib[k] << sh;
        seg |= __shfl_xor_sync(0xFFFFFFFFu, seg, 1);
        seg |= __shfl_xor_sync(0xFFFFFFFFu, seg, 2);
        seg |= __shfl_xor_sync(0xFFFFFFFFu, seg, 4);
        if ((lane & 7) == 0) {
            int mi = (k < 3) ? (b * 3 + k) : (6 + b * 3 + (k - 3));
            ((u32*)&g_mbits[mi][row])[widx] = seg;
        }
    }
}

// Erosion on bitmaps.  grid (32,12) x 256 ; thread per row
__global__ void k_erode() {
    int row = blockIdx.x * 256 + threadIdx.x;
    int mi = blockIdx.y;
    int y = row & (HY - 1);
    int z = row >> 7;
    B128 e;
    if (y == 0 || y == HY - 1 || z == 0 || z == DZ - 1) {
        e.lo = 0; e.hi = 0;
    } else {
        B128 m  = b_load(g_mbits[mi], row);
        B128 up = b_load(g_mbits[mi], row - 1);
        B128 dn = b_load(g_mbits[mi], row + 1);
        B128 fr = b_load(g_mbits[mi], row - HY);
        B128 bk = b_load(g_mbits[mi], row + HY);
        B128 ml = b_shl1(m), mr = b_shr1(m);
        e.lo = m.lo & ml.lo & mr.lo & up.lo & dn.lo & fr.lo & bk.lo;
        e.hi = m.hi & ml.hi & mr.hi & up.hi & dn.hi & fr.hi & bk.hi;
    }
    b_store(g_ebits[mi], row, e);
}

// Slab-local CC: all y-pair merges AND intra-slab z merges for 4 z-planes,
// in shared-memory UF; writes flattened parents to g_P (and zeroes g_R window).
// grid (NSLAB=16, 36) x 256 ; dynamic smem = SRUN*4 = 128 KB
__global__ void __launch_bounds__(256) k_slab() {
    __shared__ u64 sLo[SROWS], sHi[SROWS];    // occupancy per slab row
    __shared__ u64 tLo[SROWS], tHi[SROWS];    // run starts per slab row
    extern __shared__ int sP[];               // slab-local UF (128 KB)

    int tid = threadIdx.x;
    int slab = blockIdx.x;
    int p = blockIdx.y;
    int row0 = slab * SROWS;                  // global row base (z = slab*4)

    #pragma unroll
    for (int j = 0; j < 2; j++) {
        int r = tid + j * 256;
        B128 o = get_occ(p, row0 + r);
        sLo[r] = o.lo; sHi[r] = o.hi;
        B128 st = b_starts(o);
        tLo[r] = st.lo; tHi[r] = st.hi;
    }
    {
        int4 sv = make_int4(LSEN, LSEN, LSEN, LSEN);
        #pragma unroll
        for (int j = 0; j < 32; j++)
            ((int4*)sP)[tid + j * 256] = sv;
    }
    __syncthreads();

    // merge tasks: 1016 y-tasks (4 planes x 127 pairs x 2 halves)
    //            +  768 z-tasks (3 interfaces x 128 y x 2 halves)
    for (int t = tid; t < 1016 + 768; t += 256) {
        int rowA, rowB, half;
        if (t < 1016) {
            int pairIdx = t >> 1; half = t & 1;
            int zl = pairIdx / 127, yy = pairIdx % 127 + 1;
            rowA = zl * HY + yy; rowB = rowA - 1;
        } else {
            int s = t - 1016;
            int pairIdx = s >> 1; half = s & 1;
            int zl = pairIdx >> 7, y = pairIdx & 127;
            rowA = (zl + 1) * HY + y; rowB = rowA - HY;
        }
        u64 oA = half ? sHi[rowA] : sLo[rowA];
        u64 oB = half ? sHi[rowB] : sLo[rowB];
        u64 pr = oA & oB;
        if (!pr) continue;
        u64 carry = half ? ((sLo[rowA] & sLo[rowB]) >> 63) : 0ULL;
        u64 w = pr & ~((pr << 1) | carry);
        if (!w) continue;
        B128 sA = {tLo[rowA], tHi[rowA]};
        B128 sB = {tLo[rowB], tHi[rowB]};
        int boff = half * 64;
        while (w) {
            int b = __ffsll((long long)w) - 1; w &= w - 1;
            int gb = b + boff;
            l_union(sP, rowA * 64 + (b_popbelow(sA, gb + 1) - 1),
                        rowB * 64 + (b_popbelow(sB, gb + 1) - 1));
        }
    }
    __syncthreads();

    // flatten + write global parents (coalesced int4)
    {
        int gbase = slab * SRUN;
        int* Pg = g_P + (size_t)p * RCAP + gbase;
        #pragma unroll
        for (int j = 0; j < 32; j++) {
            int idx = tid + j * 256;     // int4 index in [0, 8192)
            int i = idx * 4;
            int4 o4;
            o4.x = (sP[i]     >= SRUN) ? SEN : (gbase + l_find(sP, i));
            o4.y = (sP[i + 1] >= SRUN) ? SEN : (gbase + l_find(sP, i + 1));
            o4.z = (sP[i + 2] >= SRUN) ? SEN : (gbase + l_find(sP, i + 2));
            o4.w = (sP[i + 3] >= SRUN) ? SEN : (gbase + l_find(sP, i + 3));
            ((int4*)Pg)[idx] = o4;
        }
        if (p >= 24) {
            uint4* Rg = (uint4*)(g_R + (size_t)(p - 24) * RCAP + gbase);
            uint4 zv = make_uint4(0, 0, 0, 0);
            #pragma unroll
            for (int j = 0; j < 8; j++)
                Rg[tid + j * 256] = zv;
        }
        if (p == 0 && slab == 0 && tid < NPROB) g_cnt[tid] = 0;
    }
}

// Cross-slab (z-interface) merges on slab-coarsened operands.
// 15 interfaces x 128 y x 2 halves = 3840 tasks/problem.  grid (15,36) x 256
__global__ void k_zmerge() {
    int t = blockIdx.x * 256 + threadIdx.x;   // [0, 3840)
    int pairid = t >> 1, half = t & 1;
    int p = blockIdx.y;
    int zi = (pairid >> 7) + 1, y = pairid & 127;  // interface at z = zi*4
    int rowA = (zi * ZSLAB) * HY + y;
    int rowB = rowA - HY;
    B128 oA = get_occ(p, rowA);
    B128 oB = get_occ(p, rowB);
    B128 pr = b_and(oA, oB);
    B128 ps = b_starts(pr);
    u64 w = half ? ps.hi : ps.lo;
    if (!w) return;
    B128 sA = b_starts(oA);
    B128 sB = b_starts(oB);
    int baseA = rowA * 64, baseB = rowB * 64;
    int boff = half * 64;
    int* P = g_P + (size_t)p * RCAP;
    while (w) {
        int b = __ffsll((long long)w) - 1; w &= w - 1;
        int gb = b + boff;
        uf_union(P, baseA + b_popbelow(sA, gb + 1) - 1,
                    baseB + b_popbelow(sB, gb + 1) - 1);
    }
}

// Mark bg components reaching the volume border. 4 threads/row.  grid (128,12) x 256
__global__ void k_bordermark() {
    int t = blockIdx.x * 256 + threadIdx.x;
    int row = t >> 2, w = t & 3;
    int pb = blockIdx.y;
    int p = 24 + pb;
    int y = row & (HY - 1);
    int z = row >> 7;
    B128 occ = get_occ(p, row);
    if (!b_any(occ)) return;
    int base = row * 64;
    int* P = g_P + (size_t)p * RCAP;
    u8* R = g_R + (size_t)pb * RCAP;
    B128 st = b_starts(occ);
    bool borderrow = (z == 0) || (z == DZ - 1) || (y == 0) || (y == HY - 1);
    if (borderrow) {
        u32 stw = (w < 2) ? (u32)(st.lo >> (w * 32)) : (u32)(st.hi >> ((w - 2) * 32));
        if (!stw) return;
        int k = b_popbelow(st, w * 32);
        while (stw) {
            stw &= stw - 1;
            R[uf_find(P, base + k)] = 1;
            k++;
        }
    } else {
        if (w == 0) {
            if (occ.lo & 1ULL) R[uf_find(P, base)] = 1;
        } else if (w == 3) {
            if (occ.hi >> 63) R[uf_find(P, base + b_pop(st) - 1)] = 1;
        }
    }
}

// Count roots (p<24) / cavity voxels (p>=24). 4 threads/row.  grid (128,36) x 256
__global__ void k_count() {
    int t = blockIdx.x * 256 + threadIdx.x;
    int row = t >> 2, w = t & 3;
    int p = blockIdx.y;
    B128 occ = get_occ(p, row);
    int c = 0;
    if (b_any(occ)) {
        B128 st = b_starts(occ);
        u32 stw = (w < 2) ? (u32)(st.lo >> (w * 32)) : (u32)(st.hi >> ((w - 2) * 32));
        if (stw) {
            int base = row * 64;
            int* P = g_P + (size_t)p * RCAP;
            int k = b_popbelow(st, w * 32);
            if (p < 24) {
                while (stw) {
                    stw &= stw - 1;
                    c += (P[base + k] >= RCAP);
                    k++;
                }
            } else {
                const u8* R = g_R + (size_t)(p - 24) * RCAP;
                int boff = w * 32;
                while (stw) {
                    int b = __ffs(stw) - 1; stw &= stw - 1;
                    if (!R[uf_find(P, base + k)]) c += b_runlen(occ, b + boff);
                    k++;
                }
            }
        }
    }
    #pragma unroll
    for (int off = 16; off > 0; off >>= 1)
        c += __shfl_down_sync(0xFFFFFFFFu, c, off);
    __shared__ int ssum;
    if (threadIdx.x == 0) ssum = 0;
    __syncthreads();
    if ((threadIdx.x & 31) == 0 && c) atomicAdd(&ssum, c);
    __syncthreads();
    if (threadIdx.x == 0 && ssum) atomicAdd(&g_cnt[p], ssum);
}

__device__ __forceinline__ int iabs_(int a) { return a < 0 ? -a : a; }
__device__ __forceinline__ int imax0_(int a) { return a > 0 ? a : 0; }

__global__ void k_final(float* __restrict__ out) {
    float tot = 0.0f;
    #pragma unroll
    for (int i = 0; i < 6; i++) {
        int pb0 = g_cnt[i],      tb0 = g_cnt[i + 6];
        int pbe = g_cnt[12 + i], tbe = g_cnt[12 + i + 6];
        int pcv = g_cnt[24 + i], tcv = g_cnt[24 + i + 6];
        int pb1 = imax0_(pb0 - pbe), tb1 = imax0_(tb0 - tbe);
        int pb2 = pcv / 100,         tb2 = tcv / 100;
        tot += (float)(iabs_(pb0 - tb0) + iabs_(pb1 - tb1) + iabs_(pb2 - tb2));
    }
    out[0] = 0.1f * tot / 6.0f;
}

// ---------------- launch ----------------
extern "C" void kernel_launch(void* const* d_in, const int* in_sizes, int n_in,
                              void* d_out, int out_size) {
    const float* pred   = (const float*)d_in[0];
    const int*   target = (const int*)d_in[1];
    float*       out    = (float*)d_out;

    static bool attr_set = false;
    if (!attr_set) {
        cudaFuncSetAttribute(k_slab, cudaFuncAttributeMaxDynamicSharedMemorySize,
                             SRUN * (int)sizeof(int));
        attr_set = true;
    }

    k_masks<<<2048, 256>>>(pred, target);
    k_erode<<<dim3(32, 12), 256>>>();
    k_slab<<<dim3(NSLAB, NPROB), 256, SRUN * sizeof(int)>>>();
    k_zmerge<<<dim3(15, NPROB), 256>>>();
    k_bordermark<<<dim3(128, 12), 256>>>();
    k_count<<<dim3(128, NPROB), 256>>>();
    k_final<<<1, 1>>>(out);
}

// round 15
// speedup vs baseline: 2.9891x; 2.9891x over previous
#include <cuda_runtime.h>
#include <cuda_bf16.h>
#include <stdint.h>
#include <math.h>

// Volume: D=64, H=128, W=128 ; B=2, C=4  (fixed shapes)
#define DZ 64
#define HY 128
#define WX 128
#define NVOX (DZ * HY * WX)   // 1,048,576
#define NROWS 8192            // DZ*HY rows of 128 voxels
#define NMASK 12
#define NPROB 36
#define RCAP (NROWS * 64)     // run slots per problem = 524288
#define PRUN 8192             // run slots per z-plane (128 rows * 64)
#define SEN  0x7F7F7F7F       // global sentinel (>= RCAP -> root)
#define LSEN 0x7FFFFFFF       // plane-local sentinel (>= PRUN -> root)

typedef unsigned int u32;
typedef unsigned long long u64;
typedef unsigned char u8;

// Scratch (device globals)
__device__ uint4 g_mbits[NMASK][NROWS];      // mask bitmaps, 16B/row
__device__ uint4 g_ebits[NMASK][NROWS];      // eroded bitmaps
__device__ int   g_P[(size_t)NPROB * RCAP];  // run-level UF parents (written by k_plane)
__device__ u8    g_R[(size_t)NMASK * RCAP];  // bg run border-reach flags
__device__ int   g_cnt[NPROB];

// ---------------- 128-bit row helpers ----------------
struct B128 { u64 lo, hi; };

__device__ __forceinline__ B128 b_load(const uint4* arr, int row) {
    uint4 q = arr[row];
    B128 r;
    r.lo = (u64)q.x | ((u64)q.y << 32);
    r.hi = (u64)q.z | ((u64)q.w << 32);
    return r;
}
__device__ __forceinline__ void b_store(uint4* arr, int row, B128 v) {
    arr[row] = make_uint4((u32)v.lo, (u32)(v.lo >> 32), (u32)v.hi, (u32)(v.hi >> 32));
}
__device__ __forceinline__ B128 b_and(B128 a, B128 b) { return {a.lo & b.lo, a.hi & b.hi}; }
__device__ __forceinline__ B128 b_not(B128 a) { return {~a.lo, ~a.hi}; }
__device__ __forceinline__ B128 b_shl1(B128 a) { return {a.lo << 1, (a.hi << 1) | (a.lo >> 63)}; }
__device__ __forceinline__ B128 b_shr1(B128 a) { return {(a.lo >> 1) | (a.hi << 63), a.hi >> 1}; }
__device__ __forceinline__ bool b_any(B128 a) { return (a.lo | a.hi) != 0ULL; }
__device__ __forceinline__ int  b_pop(B128 a) { return __popcll(a.lo) + __popcll(a.hi); }
__device__ __forceinline__ B128 b_starts(B128 o) { B128 s = b_shl1(o); return {o.lo & ~s.lo, o.hi & ~s.hi}; }
// popcount of start bits strictly below global bit position b (b in [0,128])
__device__ __forceinline__ int b_popbelow(B128 s, int b) {
    if (b == 0) return 0;
    if (b <= 64) {
        u64 m = (b == 64) ? ~0ULL : ((1ULL << b) - 1ULL);
        return __popcll(s.lo & m);
    }
    int bb = b - 64;
    u64 m = (bb >= 64) ? ~0ULL : ((1ULL << bb) - 1ULL);
    return __popcll(s.lo) + __popcll(s.hi & m);
}
__device__ __forceinline__ int cto64(u64 x) {
    u64 inv = ~x;
    return inv ? (__ffsll((long long)inv) - 1) : 64;
}
__device__ __forceinline__ int b_runlen(B128 o, int b) {
    B128 sh;
    if (b == 0) sh = o;
    else if (b < 64) { sh.lo = (o.lo >> b) | (o.hi << (64 - b)); sh.hi = o.hi >> b; }
    else { sh.lo = o.hi >> (b - 64); sh.hi = 0; }
    int c = cto64(sh.lo);
    if (c == 64) c += cto64(sh.hi);
    return c;
}

// ---------------- global union-find (sentinel roots: P[x] >= RCAP) --------
__device__ __forceinline__ int uf_find(int* P, int x) {
    while (true) {
        int p = P[x];
        if (p >= RCAP) return x;
        int gp = P[p];
        if (gp >= RCAP) return p;
        P[x] = gp;
        x = gp;
    }
}
__device__ __forceinline__ void uf_union(int* P, int a, int b) {
    while (true) {
        a = uf_find(P, a);
        b = uf_find(P, b);
        if (a == b) return;
        if (a > b) { int t = a; a = b; b = t; }
        int old = atomicMin(&P[b], a);
        if (old >= RCAP || old == b) return;
        b = old;
    }
}

// ---------------- plane-local union-find (shared; roots: >= PRUN) ---------
__device__ __forceinline__ int l_find(int* P, int x) {
    while (true) {
        int p = P[x];
        if (p >= PRUN) return x;
        int gp = P[p];
        if (gp >= PRUN) return p;
        P[x] = gp;
        x = gp;
    }
}
__device__ __forceinline__ void l_union(int* P, int a, int b) {
    while (true) {
        a = l_find(P, a);
        b = l_find(P, b);
        if (a == b) return;
        if (a > b) { int t = a; a = b; b = t; }
        int old = atomicMin(&P[b], a);
        if (old >= PRUN || old == b) return;
        b = old;
    }
}

// occupancy for problem p, row r
__device__ __forceinline__ B128 get_occ(int p, int row) {
    if (p < 12) return b_load(g_mbits[p], row);
    if (p < 24) return b_load(g_ebits[p - 12], row);
    return b_not(b_load(g_mbits[p - 24], row));
}

// ---------------- kernels ----------------

// Warp per (batch,row): softmax+threshold -> 6 bitmap rows.  grid 2048 x 256
__global__ void k_masks(const float* __restrict__ pred, const int* __restrict__ target) {
    int gw = blockIdx.x * 8 + (threadIdx.x >> 5);
    int lane = threadIdx.x & 31;
    int b = gw >> 13;
    int row = gw & (NROWS - 1);
    int v = row * WX + lane * 4;

    const float* pp = pred + (size_t)b * 4 * NVOX + v;
    float4 a0 = *(const float4*)(pp);
    float4 a1 = *(const float4*)(pp + NVOX);
    float4 a2 = *(const float4*)(pp + 2 * NVOX);
    float4 a3 = *(const float4*)(pp + 3 * NVOX);
    int4 t = *(const int4*)(target + (size_t)b * NVOX + v);

    float x0s[4] = {a0.x, a0.y, a0.z, a0.w};
    float x1s[4] = {a1.x, a1.y, a1.z, a1.w};
    float x2s[4] = {a2.x, a2.y, a2.z, a2.w};
    float x3s[4] = {a3.x, a3.y, a3.z, a3.w};
    u32 nib[6] = {0, 0, 0, 0, 0, 0};
    #pragma unroll
    for (int i = 0; i < 4; i++) {
        float m = fmaxf(fmaxf(x0s[i], x1s[i]), fmaxf(x2s[i], x3s[i]));
        float e0 = expf(x0s[i] - m), e1 = expf(x1s[i] - m);
        float e2 = expf(x2s[i] - m), e3 = expf(x3s[i] - m);
        float h = 0.5f * (e0 + e1 + e2 + e3);
        nib[0] |= (e1 > h) << i;
        nib[1] |= (e2 > h) << i;
        nib[2] |= (e3 > h) << i;
    }
    int ts[4] = {t.x, t.y, t.z, t.w};
    #pragma unroll
    for (int i = 0; i < 4; i++) {
        nib[3] |= (ts[i] == 1) << i;
        nib[4] |= (ts[i] == 2) << i;
        nib[5] |= (ts[i] == 3) << i;
    }
    int sh = (lane & 7) * 4;
    int widx = lane >> 3;
    #pragma unroll
    for (int k = 0; k < 6; k++) {
        u32 seg = nib[k] << sh;
        seg |= __shfl_xor_sync(0xFFFFFFFFu, seg, 1);
        seg |= __shfl_xor_sync(0xFFFFFFFFu, seg, 2);
        seg |= __shfl_xor_sync(0xFFFFFFFFu, seg, 4);
        if ((lane & 7) == 0) {
            int mi = (k < 3) ? (b * 3 + k) : (6 + b * 3 + (k - 3));
            ((u32*)&g_mbits[mi][row])[widx] = seg;
        }
    }
}

// Erosion on bitmaps.  grid (32,12) x 256 ; thread per row
__global__ void k_erode() {
    int row = blockIdx.x * 256 + threadIdx.x;
    int mi = blockIdx.y;
    int y = row & (HY - 1);
    int z = row >> 7;
    B128 e;
    if (y == 0 || y == HY - 1 || z == 0 || z == DZ - 1) {
        e.lo = 0; e.hi = 0;
    } else {
        B128 m  = b_load(g_mbits[mi], row);
        B128 up = b_load(g_mbits[mi], row - 1);
        B128 dn = b_load(g_mbits[mi], row + 1);
        B128 fr = b_load(g_mbits[mi], row - HY);
        B128 bk = b_load(g_mbits[mi], row + HY);
        B128 ml = b_shl1(m), mr = b_shr1(m);
        e.lo = m.lo & ml.lo & mr.lo & up.lo & dn.lo & fr.lo & bk.lo;
        e.hi = m.hi & ml.hi & mr.hi & up.hi & dn.hi & fr.hi & bk.hi;
    }
    b_store(g_ebits[mi], row, e);
}

// Plane-local CC: all y-pair merges for one z-plane in shared-memory UF,
// then write flattened parents to g_P (and zero g_R window, g_cnt).
// grid (DZ=64, 36) x 256
__global__ void __launch_bounds__(256) k_plane() {
    __shared__ u64 sLo[128], sHi[128];    // occupancy per row
    __shared__ u64 tLo[128], tHi[128];    // run starts per row
    __shared__ int sP[PRUN];              // plane-local UF (32 KB)

    int tid = threadIdx.x;
    int z = blockIdx.x;
    int p = blockIdx.y;

    if (tid < 128) {
        B128 o = get_occ(p, z * HY + tid);
        sLo[tid] = o.lo; sHi[tid] = o.hi;
        B128 st = b_starts(o);
        tLo[tid] = st.lo; tHi[tid] = st.hi;
    }
    {
        int4 sv = make_int4(LSEN, LSEN, LSEN, LSEN);
        #pragma unroll
        for (int j = 0; j < 8; j++)
            ((int4*)sP)[tid + j * 256] = sv;
    }
    __syncthreads();

    // y-pair merges: tasks t = (y-1)*2 + half, y in [1,128), half in {0,1}
    if (tid < 254) {
        int y = (tid >> 1) + 1, half = tid & 1;
        u64 oA = half ? sHi[y] : sLo[y];
        u64 oB = half ? sHi[y - 1] : sLo[y - 1];
        u64 pr = oA & oB;
        if (pr) {
            u64 carry = half ? ((sLo[y] & sLo[y - 1]) >> 63) : 0ULL;
            u64 w = pr & ~((pr << 1) | carry);
            if (w) {
                B128 sA = {tLo[y], tHi[y]};
                B128 sB = {tLo[y - 1], tHi[y - 1]};
                int boff = half * 64;
                while (w) {
                    int b = __ffsll((long long)w) - 1; w &= w - 1;
                    int gb = b + boff;
                    l_union(sP, y * 64 + (b_popbelow(sA, gb + 1) - 1),
                                (y - 1) * 64 + (b_popbelow(sB, gb + 1) - 1));
                }
            }
        }
    }
    __syncthreads();

    // flatten + write global parents (coalesced int4)
    {
        int gbase = z * PRUN;
        int* Pg = g_P + (size_t)p * RCAP + gbase;
        #pragma unroll
        for (int j = 0; j < 8; j++) {
            int idx = tid + j * 256;     // int4 index
            int i = idx * 4;
            int4 o4;
            o4.x = (sP[i]     >= PRUN) ? SEN : (gbase + l_find(sP, i));
            o4.y = (sP[i + 1] >= PRUN) ? SEN : (gbase + l_find(sP, i + 1));
            o4.z = (sP[i + 2] >= PRUN) ? SEN : (gbase + l_find(sP, i + 2));
            o4.w = (sP[i + 3] >= PRUN) ? SEN : (gbase + l_find(sP, i + 3));
            ((int4*)Pg)[idx] = o4;
        }
        if (p >= 24) {
            uint4* Rg = (uint4*)(g_R + (size_t)(p - 24) * RCAP + gbase);
            uint4 zv = make_uint4(0, 0, 0, 0);
            Rg[tid] = zv;
            Rg[tid + 256] = zv;
        }
        if (p == 0 && z == 0 && tid < NPROB) g_cnt[tid] = 0;
    }
}

// Cross-plane (z-pair) merges on pre-coarsened operands.
// 4 threads per pair (one per 32-bit window); 63*128=8064 pairs/problem.
// grid (126,36) x 256
__global__ void k_zmerge() {
    int t = blockIdx.x * 256 + threadIdx.x;   // [0, 32256)
    int pairid = t >> 2, w32 = t & 3;
    int p = blockIdx.y;
    int z = pairid >> 7, y = pairid & 127;    // z in [0,63) -> plane z+1 vs z
    int rowA = (z + 1) * HY + y;
    int rowB = rowA - HY;
    B128 oA = get_occ(p, rowA);
    B128 oB = get_occ(p, rowB);
    B128 pr = b_and(oA, oB);
    if (!b_any(pr)) return;
    B128 ps = b_starts(pr);
    u32 w = (w32 < 2) ? (u32)(ps.lo >> (w32 * 32)) : (u32)(ps.hi >> ((w32 - 2) * 32));
    if (!w) return;
    B128 sA = b_starts(oA);
    B128 sB = b_starts(oB);
    int baseA = rowA * 64, baseB = rowB * 64;
    int boff = w32 * 32;
    int* P = g_P + (size_t)p * RCAP;
    while (w) {
        int b = __ffs(w) - 1; w &= w - 1;
        int gb = b + boff;
        uf_union(P, baseA + b_popbelow(sA, gb + 1) - 1,
                    baseB + b_popbelow(sB, gb + 1) - 1);
    }
}

// Mark bg components reaching the volume border. 4 threads/row.  grid (128,12) x 256
__global__ void k_bordermark() {
    int t = blockIdx.x * 256 + threadIdx.x;
    int row = t >> 2, w = t & 3;
    int pb = blockIdx.y;
    int p = 24 + pb;
    int y = row & (HY - 1);
    int z = row >> 7;
    B128 occ = get_occ(p, row);
    if (!b_any(occ)) return;
    int base = row * 64;
    int* P = g_P + (size_t)p * RCAP;
    u8* R = g_R + (size_t)pb * RCAP;
    B128 st = b_starts(occ);
    bool borderrow = (z == 0) || (z == DZ - 1) || (y == 0) || (y == HY - 1);
    if (borderrow) {
        u32 stw = (w < 2) ? (u32)(st.lo >> (w * 32)) : (u32)(st.hi >> ((w - 2) * 32));
        if (!stw) return;
        int k = b_popbelow(st, w * 32);
        while (stw) {
            stw &= stw - 1;
            R[uf_find(P, base + k)] = 1;
            k++;
        }
    } else {
        if (w == 0) {
            if (occ.lo & 1ULL) R[uf_find(P, base)] = 1;
        } else if (w == 3) {
            if (occ.hi >> 63) R[uf_find(P, base + b_pop(st) - 1)] = 1;
        }
    }
}

// Count roots (p<24) / cavity voxels (p>=24). 4 threads/row.  grid (128,36) x 256
__global__ void k_count() {
    int t = blockIdx.x * 256 + threadIdx.x;
    int row = t >> 2, w = t & 3;
    int p = blockIdx.y;
    B128 occ = get_occ(p, row);
    int c = 0;
    if (b_any(occ)) {
        B128 st = b_starts(occ);
        u32 stw = (w < 2) ? (u32)(st.lo >> (w * 32)) : (u32)(st.hi >> ((w - 2) * 32));
        if (stw) {
            int base = row * 64;
            int* P = g_P + (size_t)p * RCAP;
            int k = b_popbelow(st, w * 32);
            if (p < 24) {
                while (stw) {
                    stw &= stw - 1;
                    c += (P[base + k] >= RCAP);
                    k++;
                }
            } else {
                const u8* R = g_R + (size_t)(p - 24) * RCAP;
                int boff = w * 32;
                while (stw) {
                    int b = __ffs(stw) - 1; stw &= stw - 1;
                    if (!R[uf_find(P, base + k)]) c += b_runlen(occ, b + boff);
                    k++;
                }
            }
        }
    }
    #pragma unroll
    for (int off = 16; off > 0; off >>= 1)
        c += __shfl_down_sync(0xFFFFFFFFu, c, off);
    __shared__ int ssum;
    if (threadIdx.x == 0) ssum = 0;
    __syncthreads();
    if ((threadIdx.x & 31) == 0 && c) atomicAdd(&ssum, c);
    __syncthreads();
    if (threadIdx.x == 0 && ssum) atomicAdd(&g_cnt[p], ssum);
}

__device__ __forceinline__ int iabs_(int a) { return a < 0 ? -a : a; }
__device__ __forceinline__ int imax0_(int a) { return a > 0 ? a : 0; }

__global__ void k_final(float* __restrict__ out) {
    float tot = 0.0f;
    #pragma unroll
    for (int i = 0; i < 6; i++) {
        int pb0 = g_cnt[i],      tb0 = g_cnt[i + 6];
        int pbe = g_cnt[12 + i], tbe = g_cnt[12 + i + 6];
        int pcv = g_cnt[24 + i], tcv = g_cnt[24 + i + 6];
        int pb1 = imax0_(pb0 - pbe), tb1 = imax0_(tb0 - tbe);
        int pb2 = pcv / 100,         tb2 = tcv / 100;
        tot += (float)(iabs_(pb0 - tb0) + iabs_(pb1 - tb1) + iabs_(pb2 - tb2));
    }
    out[0] = 0.1f * tot / 6.0f;
}

// ---------------- launch ----------------
extern "C" void kernel_launch(void* const* d_in, const int* in_sizes, int n_in,
                              void* d_out, int out_size) {
    const float* pred   = (const float*)d_in[0];
    const int*   target = (const int*)d_in[1];
    float*       out    = (float*)d_out;

    k_masks<<<2048, 256>>>(pred, target);
    k_erode<<<dim3(32, 12), 256>>>();
    k_plane<<<dim3(DZ, NPROB), 256>>>();
    k_zmerge<<<dim3(126, NPROB), 256>>>();
    k_bordermark<<<dim3(128, 12), 256>>>();
    k_count<<<dim3(128, NPROB), 256>>>();
    k_final<<<1, 1>>>(out);
}

// round 16
// speedup vs baseline: 3.0384x; 1.0165x over previous
#include <cuda_runtime.h>
#include <cuda_bf16.h>
#include <stdint.h>
#include <math.h>

// Volume: D=64, H=128, W=128 ; B=2, C=4  (fixed shapes)
#define DZ 64
#define HY 128
#define WX 128
#define NVOX (DZ * HY * WX)   // 1,048,576
#define NROWS 8192            // DZ*HY rows of 128 voxels
#define NMASK 12
#define NPROB 36
#define RCAP (NROWS * 64)     // run slots per problem = 524288
#define PRUN 8192             // run slots per z-plane (128 rows * 64)
#define SEN  0x7F7F7F7F       // global sentinel (>= RCAP -> root)
#define LSEN 0x7FFFFFFF       // plane-local sentinel (>= PRUN -> root)

typedef unsigned int u32;
typedef unsigned long long u64;
typedef unsigned char u8;

// Scratch (device globals)
__device__ uint4 g_mbits[NMASK][NROWS];      // mask bitmaps, 16B/row
__device__ uint4 g_ebits[NMASK][NROWS];      // eroded bitmaps
__device__ int   g_P[(size_t)NPROB * RCAP];  // run-level UF parents (written by k_plane)
__device__ u8    g_R[(size_t)NMASK * RCAP];  // bg run border-reach flags
__device__ int   g_cnt[NPROB];

// ---------------- 128-bit row helpers ----------------
struct B128 { u64 lo, hi; };

__device__ __forceinline__ B128 b_load(const uint4* arr, int row) {
    uint4 q = arr[row];
    B128 r;
    r.lo = (u64)q.x | ((u64)q.y << 32);
    r.hi = (u64)q.z | ((u64)q.w << 32);
    return r;
}
__device__ __forceinline__ void b_store(uint4* arr, int row, B128 v) {
    arr[row] = make_uint4((u32)v.lo, (u32)(v.lo >> 32), (u32)v.hi, (u32)(v.hi >> 32));
}
__device__ __forceinline__ B128 b_and(B128 a, B128 b) { return {a.lo & b.lo, a.hi & b.hi}; }
__device__ __forceinline__ B128 b_not(B128 a) { return {~a.lo, ~a.hi}; }
__device__ __forceinline__ B128 b_shl1(B128 a) { return {a.lo << 1, (a.hi << 1) | (a.lo >> 63)}; }
__device__ __forceinline__ B128 b_shr1(B128 a) { return {(a.lo >> 1) | (a.hi << 63), a.hi >> 1}; }
__device__ __forceinline__ bool b_any(B128 a) { return (a.lo | a.hi) != 0ULL; }
__device__ __forceinline__ int  b_pop(B128 a) { return __popcll(a.lo) + __popcll(a.hi); }
__device__ __forceinline__ B128 b_starts(B128 o) { B128 s = b_shl1(o); return {o.lo & ~s.lo, o.hi & ~s.hi}; }
// popcount of start bits strictly below global bit position b (b in [0,128])
__device__ __forceinline__ int b_popbelow(B128 s, int b) {
    if (b == 0) return 0;
    if (b <= 64) {
        u64 m = (b == 64) ? ~0ULL : ((1ULL << b) - 1ULL);
        return __popcll(s.lo & m);
    }
    int bb = b - 64;
    u64 m = (bb >= 64) ? ~0ULL : ((1ULL << bb) - 1ULL);
    return __popcll(s.lo) + __popcll(s.hi & m);
}
__device__ __forceinline__ int cto64(u64 x) {
    u64 inv = ~x;
    return inv ? (__ffsll((long long)inv) - 1) : 64;
}
__device__ __forceinline__ int b_runlen(B128 o, int b) {
    B128 sh;
    if (b == 0) sh = o;
    else if (b < 64) { sh.lo = (o.lo >> b) | (o.hi << (64 - b)); sh.hi = o.hi >> b; }
    else { sh.lo = o.hi >> (b - 64); sh.hi = 0; }
    int c = cto64(sh.lo);
    if (c == 64) c += cto64(sh.hi);
    return c;
}

// ---------------- global union-find (sentinel roots: P[x] >= RCAP) --------
__device__ __forceinline__ int uf_find(int* P, int x) {
    while (true) {
        int p = P[x];
        if (p >= RCAP) return x;
        int gp = P[p];
        if (gp >= RCAP) return p;
        P[x] = gp;
        x = gp;
    }
}
// returns 1 iff this call merged two distinct components (displaced a root)
__device__ __forceinline__ int uf_union(int* P, int a, int b) {
    while (true) {
        a = uf_find(P, a);
        b = uf_find(P, b);
        if (a == b) return 0;
        if (a > b) { int t = a; a = b; b = t; }
        int old = atomicMin(&P[b], a);
        if (old >= RCAP) return 1;   // we displaced root b
        b = old;                      // b already displaced; continue
    }
}

// ---------------- plane-local union-find (shared; roots: >= PRUN) ---------
__device__ __forceinline__ int l_find(int* P, int x) {
    while (true) {
        int p = P[x];
        if (p >= PRUN) return x;
        int gp = P[p];
        if (gp >= PRUN) return p;
        P[x] = gp;
        x = gp;
    }
}
__device__ __forceinline__ int l_union(int* P, int a, int b) {
    while (true) {
        a = l_find(P, a);
        b = l_find(P, b);
        if (a == b) return 0;
        if (a > b) { int t = a; a = b; b = t; }
        int old = atomicMin(&P[b], a);
        if (old >= PRUN) return 1;
        b = old;
    }
}

// occupancy for problem p, row r
__device__ __forceinline__ B128 get_occ(int p, int row) {
    if (p < 12) return b_load(g_mbits[p], row);
    if (p < 24) return b_load(g_ebits[p - 12], row);
    return b_not(b_load(g_mbits[p - 24], row));
}

// ---------------- kernels ----------------

// Warp per (batch,row): softmax+threshold -> 6 bitmap rows.  grid 2048 x 256
__global__ void k_masks(const float* __restrict__ pred, const int* __restrict__ target) {
    int gw = blockIdx.x * 8 + (threadIdx.x >> 5);
    int lane = threadIdx.x & 31;
    int b = gw >> 13;
    int row = gw & (NROWS - 1);
    int v = row * WX + lane * 4;

    const float* pp = pred + (size_t)b * 4 * NVOX + v;
    float4 a0 = *(const float4*)(pp);
    float4 a1 = *(const float4*)(pp + NVOX);
    float4 a2 = *(const float4*)(pp + 2 * NVOX);
    float4 a3 = *(const float4*)(pp + 3 * NVOX);
    int4 t = *(const int4*)(target + (size_t)b * NVOX + v);

    float x0s[4] = {a0.x, a0.y, a0.z, a0.w};
    float x1s[4] = {a1.x, a1.y, a1.z, a1.w};
    float x2s[4] = {a2.x, a2.y, a2.z, a2.w};
    float x3s[4] = {a3.x, a3.y, a3.z, a3.w};
    u32 nib[6] = {0, 0, 0, 0, 0, 0};
    #pragma unroll
    for (int i = 0; i < 4; i++) {
        float m = fmaxf(fmaxf(x0s[i], x1s[i]), fmaxf(x2s[i], x3s[i]));
        float e0 = expf(x0s[i] - m), e1 = expf(x1s[i] - m);
        float e2 = expf(x2s[i] - m), e3 = expf(x3s[i] - m);
        float h = 0.5f * (e0 + e1 + e2 + e3);
        nib[0] |= (e1 > h) << i;
        nib[1] |= (e2 > h) << i;
        nib[2] |= (e3 > h) << i;
    }
    int ts[4] = {t.x, t.y, t.z, t.w};
    #pragma unroll
    for (int i = 0; i < 4; i++) {
        nib[3] |= (ts[i] == 1) << i;
        nib[4] |= (ts[i] == 2) << i;
        nib[5] |= (ts[i] == 3) << i;
    }
    int sh = (lane & 7) * 4;
    int widx = lane >> 3;
    #pragma unroll
    for (int k = 0; k < 6; k++) {
        u32 seg = nib[k] << sh;
        seg |= __shfl_xor_sync(0xFFFFFFFFu, seg, 1);
        seg |= __shfl_xor_sync(0xFFFFFFFFu, seg, 2);
        seg |= __shfl_xor_sync(0xFFFFFFFFu, seg, 4);
        if ((lane & 7) == 0) {
            int mi = (k < 3) ? (b * 3 + k) : (6 + b * 3 + (k - 3));
            ((u32*)&g_mbits[mi][row])[widx] = seg;
        }
    }
}

// Erosion on bitmaps + g_cnt zeroing.  grid (32,12) x 256 ; thread per row
__global__ void k_erode() {
    if (blockIdx.x == 0 && blockIdx.y == 0 && threadIdx.x < NPROB)
        g_cnt[threadIdx.x] = 0;
    int row = blockIdx.x * 256 + threadIdx.x;
    int mi = blockIdx.y;
    int y = row & (HY - 1);
    int z = row >> 7;
    B128 e;
    if (y == 0 || y == HY - 1 || z == 0 || z == DZ - 1) {
        e.lo = 0; e.hi = 0;
    } else {
        B128 m  = b_load(g_mbits[mi], row);
        B128 up = b_load(g_mbits[mi], row - 1);
        B128 dn = b_load(g_mbits[mi], row + 1);
        B128 fr = b_load(g_mbits[mi], row - HY);
        B128 bk = b_load(g_mbits[mi], row + HY);
        B128 ml = b_shl1(m), mr = b_shr1(m);
        e.lo = m.lo & ml.lo & mr.lo & up.lo & dn.lo & fr.lo & bk.lo;
        e.hi = m.hi & ml.hi & mr.hi & up.hi & dn.hi & fr.hi & bk.hi;
    }
    b_store(g_ebits[mi], row, e);
}

// Plane-local CC: all y-pair merges for one z-plane in shared-memory UF,
// write flattened parents to g_P, zero g_R window, and for fg problems
// accumulate (runs - displacements) into g_cnt[p].
// grid (DZ=64, 36) x 256
__global__ void __launch_bounds__(256) k_plane() {
    __shared__ u64 sLo[128], sHi[128];    // occupancy per row
    __shared__ u64 tLo[128], tHi[128];    // run starts per row
    __shared__ int sP[PRUN];              // plane-local UF (32 KB)
    __shared__ int sAcc;

    int tid = threadIdx.x;
    int z = blockIdx.x;
    int p = blockIdx.y;

    if (tid == 0) sAcc = 0;
    int myRuns = 0;
    if (tid < 128) {
        B128 o = get_occ(p, z * HY + tid);
        sLo[tid] = o.lo; sHi[tid] = o.hi;
        B128 st = b_starts(o);
        tLo[tid] = st.lo; tHi[tid] = st.hi;
        myRuns = b_pop(st);
    }
    {
        int4 sv = make_int4(LSEN, LSEN, LSEN, LSEN);
        #pragma unroll
        for (int j = 0; j < 8; j++)
            ((int4*)sP)[tid + j * 256] = sv;
    }
    __syncthreads();

    // y-pair merges: tasks t = (y-1)*2 + half, y in [1,128), half in {0,1}
    int myDisp = 0;
    if (tid < 254) {
        int y = (tid >> 1) + 1, half = tid & 1;
        u64 oA = half ? sHi[y] : sLo[y];
        u64 oB = half ? sHi[y - 1] : sLo[y - 1];
        u64 pr = oA & oB;
        if (pr) {
            u64 carry = half ? ((sLo[y] & sLo[y - 1]) >> 63) : 0ULL;
            u64 w = pr & ~((pr << 1) | carry);
            if (w) {
                B128 sA = {tLo[y], tHi[y]};
                B128 sB = {tLo[y - 1], tHi[y - 1]};
                int boff = half * 64;
                while (w) {
                    int b = __ffsll((long long)w) - 1; w &= w - 1;
                    int gb = b + boff;
                    myDisp += l_union(sP, y * 64 + (b_popbelow(sA, gb + 1) - 1),
                                          (y - 1) * 64 + (b_popbelow(sB, gb + 1) - 1));
                }
            }
        }
    }
    __syncthreads();

    // flatten + write global parents (coalesced int4)
    {
        int gbase = z * PRUN;
        int* Pg = g_P + (size_t)p * RCAP + gbase;
        #pragma unroll
        for (int j = 0; j < 8; j++) {
            int idx = tid + j * 256;     // int4 index
            int i = idx * 4;
            int4 o4;
            o4.x = (sP[i]     >= PRUN) ? SEN : (gbase + l_find(sP, i));
            o4.y = (sP[i + 1] >= PRUN) ? SEN : (gbase + l_find(sP, i + 1));
            o4.z = (sP[i + 2] >= PRUN) ? SEN : (gbase + l_find(sP, i + 2));
            o4.w = (sP[i + 3] >= PRUN) ? SEN : (gbase + l_find(sP, i + 3));
            ((int4*)Pg)[idx] = o4;
        }
        if (p >= 24) {
            uint4* Rg = (uint4*)(g_R + (size_t)(p - 24) * RCAP + gbase);
            uint4 zv = make_uint4(0, 0, 0, 0);
            Rg[tid] = zv;
            Rg[tid + 256] = zv;
        }
    }

    // fg component accounting: g_cnt[p] += runs - displacements
    if (p < 24) {
        int v = myRuns - myDisp;
        #pragma unroll
        for (int off = 16; off > 0; off >>= 1)
            v += __shfl_down_sync(0xFFFFFFFFu, v, off);
        if ((tid & 31) == 0 && v) atomicAdd(&sAcc, v);
        __syncthreads();
        if (tid == 0 && sAcc) atomicAdd(&g_cnt[p], sAcc);
    }
}

// Cross-plane (z-pair) merges on pre-coarsened operands.
// 4 threads per pair (one per 32-bit window); 63*128=8064 pairs/problem.
// Counts displacements, subtracts from g_cnt[p] (fg problems).
// grid (126,36) x 256
__global__ void k_zmerge() {
    int t = blockIdx.x * 256 + threadIdx.x;   // [0, 32256) == 4*8064 exactly
    int pairid = t >> 2, w32 = t & 3;
    int p = blockIdx.y;
    int z = pairid >> 7, y = pairid & 127;    // z in [0,63) -> plane z+1 vs z
    int rowA = (z + 1) * HY + y;
    int rowB = rowA - HY;
    B128 oA = get_occ(p, rowA);
    B128 oB = get_occ(p, rowB);
    B128 pr = b_and(oA, oB);
    int disp = 0;
    if (b_any(pr)) {
        B128 ps = b_starts(pr);
        u32 w = (w32 < 2) ? (u32)(ps.lo >> (w32 * 32)) : (u32)(ps.hi >> ((w32 - 2) * 32));
        if (w) {
            B128 sA = b_starts(oA);
            B128 sB = b_starts(oB);
            int baseA = rowA * 64, baseB = rowB * 64;
            int boff = w32 * 32;
            int* P = g_P + (size_t)p * RCAP;
            while (w) {
                int b = __ffs(w) - 1; w &= w - 1;
                int gb = b + boff;
                disp += uf_union(P, baseA + b_popbelow(sA, gb + 1) - 1,
                                     baseB + b_popbelow(sB, gb + 1) - 1);
            }
        }
    }
    if (p < 24) {
        #pragma unroll
        for (int off = 16; off > 0; off >>= 1)
            disp += __shfl_down_sync(0xFFFFFFFFu, disp, off);
        __shared__ int ssum;
        if (threadIdx.x == 0) ssum = 0;
        __syncthreads();
        if ((threadIdx.x & 31) == 0 && disp) atomicAdd(&ssum, disp);
        __syncthreads();
        if (threadIdx.x == 0 && ssum) atomicSub(&g_cnt[p], ssum);
    }
}

// Mark bg components reaching the volume border. 4 threads/row.  grid (128,12) x 256
__global__ void k_bordermark() {
    int t = blockIdx.x * 256 + threadIdx.x;
    int row = t >> 2, w = t & 3;
    int pb = blockIdx.y;
    int p = 24 + pb;
    int y = row & (HY - 1);
    int z = row >> 7;
    B128 occ = get_occ(p, row);
    if (!b_any(occ)) return;
    int base = row * 64;
    int* P = g_P + (size_t)p * RCAP;
    u8* R = g_R + (size_t)pb * RCAP;
    B128 st = b_starts(occ);
    bool borderrow = (z == 0) || (z == DZ - 1) || (y == 0) || (y == HY - 1);
    if (borderrow) {
        u32 stw = (w < 2) ? (u32)(st.lo >> (w * 32)) : (u32)(st.hi >> ((w - 2) * 32));
        if (!stw) return;
        int k = b_popbelow(st, w * 32);
        while (stw) {
            stw &= stw - 1;
            R[uf_find(P, base + k)] = 1;
            k++;
        }
    } else {
        if (w == 0) {
            if (occ.lo & 1ULL) R[uf_find(P, base)] = 1;
        } else if (w == 3) {
            if (occ.hi >> 63) R[uf_find(P, base + b_pop(st) - 1)] = 1;
        }
    }
}

// Cavity volume for bg problems only. 4 threads/row.  grid (128,12) x 256
__global__ void k_countbg() {
    int t = blockIdx.x * 256 + threadIdx.x;
    int row = t >> 2, w = t & 3;
    int pb = blockIdx.y;
    int p = 24 + pb;
    B128 occ = get_occ(p, row);
    int c = 0;
    if (b_any(occ)) {
        B128 st = b_starts(occ);
        u32 stw = (w < 2) ? (u32)(st.lo >> (w * 32)) : (u32)(st.hi >> ((w - 2) * 32));
        if (stw) {
            int base = row * 64;
            int* P = g_P + (size_t)p * RCAP;
            const u8* R = g_R + (size_t)pb * RCAP;
            int k = b_popbelow(st, w * 32);
            int boff = w * 32;
            while (stw) {
                int b = __ffs(stw) - 1; stw &= stw - 1;
                if (!R[uf_find(P, base + k)]) c += b_runlen(occ, b + boff);
                k++;
            }
        }
    }
    #pragma unroll
    for (int off = 16; off > 0; off >>= 1)
        c += __shfl_down_sync(0xFFFFFFFFu, c, off);
    __shared__ int ssum;
    if (threadIdx.x == 0) ssum = 0;
    __syncthreads();
    if ((threadIdx.x & 31) == 0 && c) atomicAdd(&ssum, c);
    __syncthreads();
    if (threadIdx.x == 0 && ssum) atomicAdd(&g_cnt[p], ssum);
}

__device__ __forceinline__ int iabs_(int a) { return a < 0 ? -a : a; }
__device__ __forceinline__ int imax0_(int a) { return a > 0 ? a : 0; }

__global__ void k_final(float* __restrict__ out) {
    float tot = 0.0f;
    #pragma unroll
    for (int i = 0; i < 6; i++) {
        int pb0 = g_cnt[i],      tb0 = g_cnt[i + 6];
        int pbe = g_cnt[12 + i], tbe = g_cnt[12 + i + 6];
        int pcv = g_cnt[24 + i], tcv = g_cnt[24 + i + 6];
        int pb1 = imax0_(pb0 - pbe), tb1 = imax0_(tb0 - tbe);
        int pb2 = pcv / 100,         tb2 = tcv / 100;
        tot += (float)(iabs_(pb0 - tb0) + iabs_(pb1 - tb1) + iabs_(pb2 - tb2));
    }
    out[0] = 0.1f * tot / 6.0f;
}

// ---------------- launch ----------------
extern "C" void kernel_launch(void* const* d_in, const int* in_sizes, int n_in,
                              void* d_out, int out_size) {
    const float* pred   = (const float*)d_in[0];
    const int*   target = (const int*)d_in[1];
    float*       out    = (float*)d_out;

    k_masks<<<2048, 256>>>(pred, target);
    k_erode<<<dim3(32, 12), 256>>>();
    k_plane<<<dim3(DZ, NPROB), 256>>>();
    k_zmerge<<<dim3(126, NPROB), 256>>>();
    k_bordermark<<<dim3(128, 12), 256>>>();
    k_countbg<<<dim3(128, 12), 256>>>();
    k_final<<<1, 1>>>(out);
}